// round 15
// baseline (speedup 1.0000x reference)
#include <cuda_runtime.h>
#include <cuda_bf16.h>
#include <cuda_fp16.h>
#include <cstdint>

// ===== Problem constants =====
#define B_    2
#define S_    2048
#define HID_  4096
#define NH_   32
#define NKV_  8
#define HD_   128
#define QSZ   (NH_ * HD_)
#define KVSZ  (NKV_ * HD_)
#define OSZ   (QSZ + 2 * KVSZ)     // 6144
#define TOK   (B_ * S_)            // 4096
#define SCALING 0.08838834764831843f

// ===== Scratch =====
__device__ __half g_hs[TOK * HID_];
__device__ __half g_wq[OSZ * HID_];
__device__ __half g_wo[HID_ * QSZ];
__device__ __half g_q [TOK * QSZ];
__device__ __half g_k [TOK * KVSZ];
__device__ __half g_v [TOK * KVSZ];
__device__ __half g_at[TOK * QSZ];

// ============================================================================
// PTX helpers
// ============================================================================
__device__ __forceinline__ uint32_t smem_u32(const void* p) {
    uint32_t a;
    asm("{ .reg .u64 t; cvta.to.shared.u64 t, %1; cvt.u32.u64 %0, t; }" : "=r"(a) : "l"(p));
    return a;
}
__device__ __forceinline__ void ldmatrix_x4(uint32_t& r0, uint32_t& r1,
                                            uint32_t& r2, uint32_t& r3, uint32_t addr) {
    asm volatile("ldmatrix.sync.aligned.m8n8.x4.shared.b16 {%0,%1,%2,%3}, [%4];"
                 : "=r"(r0), "=r"(r1), "=r"(r2), "=r"(r3) : "r"(addr));
}
__device__ __forceinline__ void ldmatrix_x4t(uint32_t& r0, uint32_t& r1,
                                             uint32_t& r2, uint32_t& r3, uint32_t addr) {
    asm volatile("ldmatrix.sync.aligned.m8n8.x4.trans.shared.b16 {%0,%1,%2,%3}, [%4];"
                 : "=r"(r0), "=r"(r1), "=r"(r2), "=r"(r3) : "r"(addr));
}
__device__ __forceinline__ void mma_f16(float* d, const uint32_t* a, uint32_t b0, uint32_t b1) {
    asm volatile(
        "mma.sync.aligned.m16n8k16.row.col.f32.f16.f16.f32 "
        "{%0,%1,%2,%3}, {%4,%5,%6,%7}, {%8,%9}, {%0,%1,%2,%3};"
        : "+f"(d[0]), "+f"(d[1]), "+f"(d[2]), "+f"(d[3])
        : "r"(a[0]), "r"(a[1]), "r"(a[2]), "r"(a[3]), "r"(b0), "r"(b1));
}
__device__ __forceinline__ void cp_async16(uint32_t s, const void* g) {
    asm volatile("cp.async.cg.shared.global [%0], [%1], 16;" :: "r"(s), "l"(g) : "memory");
}
#define CP_COMMIT() asm volatile("cp.async.commit_group;" ::: "memory")
#define CP_WAIT1()  asm volatile("cp.async.wait_group 1;" ::: "memory")
#define CP_WAIT0()  asm volatile("cp.async.wait_group 0;" ::: "memory")

__device__ __forceinline__ uint32_t pack_hi_h(float a, float b) {
    __half2 h = __floats2half2_rn(a, b);
    return *(uint32_t*)&h;
}

// ============================================================================
// fused convert kernel
// ============================================================================
#define N4_HS (TOK * HID_ / 4)
#define N4_WQ (OSZ * HID_ / 4)
#define N4_WO (HID_ * QSZ / 4)
#define N4_TOTAL (N4_HS + N4_WQ + N4_WO)

__global__ __launch_bounds__(256) void cvt_all_kernel(const float* __restrict__ hs,
                                                      const float* __restrict__ wq,
                                                      const float* __restrict__ wo,
                                                      __half* __restrict__ hsO,
                                                      __half* __restrict__ wqO,
                                                      __half* __restrict__ woO) {
    int i = blockIdx.x * blockDim.x + threadIdx.x;
    const float* in;
    __half* o;
    if (i < N4_HS)                 { in = hs; o = hsO; }
    else if (i < N4_HS + N4_WQ)    { in = wq; o = wqO; i -= N4_HS; }
    else if (i < N4_TOTAL)         { in = wo; o = woO; i -= N4_HS + N4_WQ; }
    else return;
    float4 v = ((const float4*)in)[i];
    ((uint2*)o)[i] = make_uint2(pack_hi_h(v.x, v.y), pack_hi_h(v.z, v.w));
}

// ============================================================================
// GEMM config: 256x128 CTA tile, 512 threads (16 warps, 4m x 4n, warp tile
// 64x32), 3-stage cp.async, 1 CTA/SM (162 KB smem). MMAs per chunk-boundary
// doubled vs 128x128; B global traffic halved.
// ============================================================================
#define GBK    64
#define GSTR   72
#define GMAT_A (256 * GSTR * 2)      // 36864 B
#define GMAT_B (128 * GSTR * 2)      // 18432 B
#define GSTAGEB (GMAT_A + GMAT_B)    // 55296 B
#define GEMM_SMEM (3 * GSTAGEB)      // 165888 B

#define GEMM_MAINLOOP(A_, B_ptr, Kdim)                                            \
    const __half* Aptr = A_;                                                      \
    const __half* Bptr = B_ptr;                                                   \
    float acc[4][4][4];                                                           \
    _Pragma("unroll") for (int i = 0; i < 4; i++)                                 \
        _Pragma("unroll") for (int j = 0; j < 4; j++)                             \
            _Pragma("unroll") for (int k = 0; k < 4; k++) acc[i][j][k] = 0.0f;    \
    const int nchunk = (Kdim) / GBK;                                              \
    auto issue = [&](int g) {                                                     \
        const int s = g % 3;                                                      \
        const uint32_t stg = sb + s * GSTAGEB;                                    \
        const int k0 = g * GBK;                                                   \
        _Pragma("unroll") for (int i = 0; i < 4; i++) {                           \
            int id  = t + i * 512;             /* 0..2047: A 256 rows x 8 units */\
            int row = id >> 3, c = id & 7;                                        \
            cp_async16(stg + (uint32_t)(row * GSTR + c * 8) * 2,                  \
                       Aptr + (size_t)row * (Kdim) + k0 + c * 8);                 \
        }                                                                         \
        _Pragma("unroll") for (int i = 0; i < 2; i++) {                           \
            int id  = t + i * 512;             /* 0..1023: B 128 rows x 8 units */\
            int row = id >> 3, c = id & 7;                                        \
            cp_async16(stg + GMAT_A + (uint32_t)(row * GSTR + c * 8) * 2,         \
                       Bptr + (size_t)row * (Kdim) + k0 + c * 8);                 \
        }                                                                         \
        CP_COMMIT();                                                              \
    };                                                                            \
    auto compute = [&](int st) {                                                  \
        const uint32_t base = sb + st * GSTAGEB;                                  \
        const uint32_t aOff = (uint32_t)((wm * 64 + (lane & 15)) * GSTR + (lane >> 4) * 8) * 2; \
        const uint32_t bOff = GMAT_A + (uint32_t)((wn * 32 + (lane & 15)) * GSTR + (lane >> 4) * 8) * 2; \
        _Pragma("unroll") for (int kk = 0; kk < 4; kk++) {                        \
            const uint32_t ko = (uint32_t)(kk * 16) * 2;                          \
            uint32_t af[4][4];                                                    \
            _Pragma("unroll") for (int mt = 0; mt < 4; mt++) {                    \
                uint32_t off = aOff + (uint32_t)(mt * 16 * GSTR) * 2 + ko;        \
                ldmatrix_x4(af[mt][0], af[mt][1], af[mt][2], af[mt][3], base + off); \
            }                                                                     \
            uint32_t bf[2][4];                                                    \
            _Pragma("unroll") for (int g = 0; g < 2; g++) {                       \
                uint32_t off = bOff + (uint32_t)(g * 16 * GSTR) * 2 + ko;         \
                ldmatrix_x4(bf[g][0], bf[g][1], bf[g][2], bf[g][3], base + off);  \
            }                                                                     \
            _Pragma("unroll") for (int mt = 0; mt < 4; mt++) {                    \
                _Pragma("unroll") for (int g = 0; g < 2; g++) {                   \
                    mma_f16(acc[mt][2 * g],     af[mt], bf[g][0], bf[g][2]);      \
                    mma_f16(acc[mt][2 * g + 1], af[mt], bf[g][1], bf[g][3]);      \
                }                                                                 \
            }                                                                     \
        }                                                                         \
    };                                                                            \
    issue(0); issue(1);                                                           \
    for (int c = 0; c < nchunk; c++) {                                            \
        if (c < nchunk - 1) { CP_WAIT1(); } else { CP_WAIT0(); }                  \
        __syncthreads();                                                          \
        if (c + 2 < nchunk) issue(c + 2);                                         \
        compute(c % 3);                                                           \
    }

// ============================================================================
// GEMM2: C[M,N] = A * B^T, fp32 out. M-blocks of 256 rows.
// ============================================================================
__global__ __launch_bounds__(512, 1) void gemm_h1(const __half* __restrict__ A,
                                                  const __half* __restrict__ Bw,
                                                  float* __restrict__ C,
                                                  int N, int K, int nBlkN) {
    extern __shared__ char sm[];
    const uint32_t sb = smem_u32(sm);

    int lin = blockIdx.x;
    int grp = lin / (8 * nBlkN);
    int rem = lin - grp * (8 * nBlkN);
    int bm  = grp * 8 + (rem & 7);
    int bn  = rem >> 3;

    const int t = threadIdx.x, lane = t & 31, wid = t >> 5;
    const int wm = wid & 3, wn = wid >> 2;   // 4m x 4n, warp tile 64x32

    GEMM_MAINLOOP(A + (size_t)bm * 256 * K, Bw + (size_t)bn * 128 * K, K)

    const int rowBase = bm * 256 + wm * 64 + (lane >> 2);
    const int colBase = bn * 128 + wn * 32 + (lane & 3) * 2;
#pragma unroll
    for (int mt = 0; mt < 4; mt++) {
#pragma unroll
        for (int nt = 0; nt < 4; nt++) {
            float* c0 = C + (size_t)(rowBase + mt * 16) * N + colBase + nt * 8;
            *(float2*)c0                   = make_float2(acc[mt][nt][0], acc[mt][nt][1]);
            *(float2*)(c0 + (size_t)8 * N) = make_float2(acc[mt][nt][2], acc[mt][nt][3]);
        }
    }
}

// ============================================================================
// GEMM1 + fused RoPE + fp16 epilogue. M-blocks of 256 rows.
// bn<32 -> Q head bn; 32..39 -> K head; 40..47 -> V head.
// ============================================================================
#define TSTR 132

__global__ __launch_bounds__(512, 1) void gemm_qkv(const __half* __restrict__ A,
                                                   const __half* __restrict__ Bw,
                                                   const float* __restrict__ cosb,
                                                   const float* __restrict__ sinb,
                                                   __half* __restrict__ qOut,
                                                   __half* __restrict__ kOut,
                                                   __half* __restrict__ vOut) {
    extern __shared__ char sm[];
    const uint32_t sb = smem_u32(sm);
    const int nBlkN = OSZ / 128;             // 48

    int lin = blockIdx.x;
    int grp = lin / (8 * nBlkN);
    int rem = lin - grp * (8 * nBlkN);
    int bm  = grp * 8 + (rem & 7);
    int bn  = rem >> 3;

    const int t = threadIdx.x, lane = t & 31, wid = t >> 5;
    const int wm = wid & 3, wn = wid >> 2;

    GEMM_MAINLOOP(A + (size_t)bm * 256 * HID_, Bw + (size_t)bn * 128 * HID_, HID_)

    // ---- epilogue: acc -> smem fp32 tile (256 x 132 = 135168 B) ----
    __syncthreads();
    float* tile = (float*)sm;
    {
        const int r0 = wm * 64 + (lane >> 2);
        const int c0 = wn * 32 + (lane & 3) * 2;
#pragma unroll
        for (int mt = 0; mt < 4; mt++) {
#pragma unroll
            for (int nt = 0; nt < 4; nt++) {
                int r = r0 + mt * 16, c = c0 + nt * 8;
                *(float2*)&tile[r * TSTR + c]       = make_float2(acc[mt][nt][0], acc[mt][nt][1]);
                *(float2*)&tile[(r + 8) * TSTR + c] = make_float2(acc[mt][nt][2], acc[mt][nt][3]);
            }
        }
    }
    __syncthreads();

    // 512 threads: row r = t>>1 (0..255), half hh = t&1
    const int r  = t >> 1;
    const int hh = t & 1;
    const int tok = bm * 256 + r;
    const float* tr = tile + r * TSTR;

    if (bn < 40) {
        const float4* cp = (const float4*)(cosb + (size_t)tok * HD_);
        const float4* sp = (const float4*)(sinb + (size_t)tok * HD_);
        const bool isQ = bn < 32;
        size_t base = isQ ? ((size_t)tok * QSZ + bn * 128)
                          : ((size_t)tok * KVSZ + (bn - 32) * 128);
        __half* dst = isQ ? qOut : kOut;
        const float sc = isQ ? SCALING : 1.0f;
#pragma unroll
        for (int i = 0; i < 8; i++) {
            int d = hh * 32 + i * 4;
            float4 x1 = *(const float4*)&tr[d];
            float4 x2 = *(const float4*)&tr[d + 64];
            float4 c1 = cp[d >> 2],        s1 = sp[d >> 2];
            float4 c2 = cp[(d + 64) >> 2], s2 = sp[(d + 64) >> 2];
            float4 y1 = make_float4((x1.x * c1.x - x2.x * s1.x) * sc, (x1.y * c1.y - x2.y * s1.y) * sc,
                                    (x1.z * c1.z - x2.z * s1.z) * sc, (x1.w * c1.w - x2.w * s1.w) * sc);
            float4 y2 = make_float4((x2.x * c2.x + x1.x * s2.x) * sc, (x2.y * c2.y + x1.y * s2.y) * sc,
                                    (x2.z * c2.z + x1.z * s2.z) * sc, (x2.w * c2.w + x1.w * s2.w) * sc);
            *(uint2*)(dst + base + d)      = make_uint2(pack_hi_h(y1.x, y1.y), pack_hi_h(y1.z, y1.w));
            *(uint2*)(dst + base + d + 64) = make_uint2(pack_hi_h(y2.x, y2.y), pack_hi_h(y2.z, y2.w));
        }
    } else {
        size_t base = (size_t)tok * KVSZ + (bn - 40) * 128;
#pragma unroll
        for (int i = 0; i < 16; i++) {
            int d = hh * 64 + i * 4;
            float4 x = *(const float4*)&tr[d];
            *(uint2*)(vOut + base + d) = make_uint2(pack_hi_h(x.x, x.y), pack_hi_h(x.z, x.w));
        }
    }
}

// ============================================================================
// Tensor-core flash attention (unchanged from R14)
// ============================================================================
#define ASTR 136
#define AQB  (128 * ASTR * 2)
#define AKB  (64 * ASTR * 2)
#define OFF_Q 0
#define OFF_KV(s) (AQB + (s) * 2 * AKB)
#define ATTN_SMEM (AQB + 4 * AKB)

__global__ __launch_bounds__(256, 2) void attn_tc(const __half* __restrict__ qp,
                                                  const __half* __restrict__ kp,
                                                  const __half* __restrict__ vp,
                                                  __half* __restrict__ outh) {
    extern __shared__ char sm[];
    const uint32_t sb = smem_u32(sm);

    const int qt = (int)gridDim.x - 1 - (int)blockIdx.x;
    const int bh = blockIdx.y;
    const int b  = bh >> 5;
    const int h  = bh & 31;
    const int kvh = h >> 2;

    const __half* kbase = kp + (size_t)b * S_ * KVSZ + kvh * HD_;
    const __half* vbase = vp + (size_t)b * S_ * KVSZ + kvh * HD_;

    const int t = threadIdx.x, lane = t & 31, wid = t >> 5;
    const int q0 = qt * 128;
    const int wRow = wid * 16;

#pragma unroll
    for (int i = 0; i < 8; i++) {
        int idx = t + i * 256;
        int r   = idx >> 4;
        int u   = idx & 15;
        size_t src = (size_t)(b * S_ + q0 + r) * QSZ + h * HD_ + u * 8;
        *(uint4*)(sm + OFF_Q + (uint32_t)(r * ASTR + u * 8) * 2) = *(const uint4*)(qp + src);
    }

    const int nkv = qt * 2 + 2;

    auto issue_kv = [&](int kt) {
        const int s = kt & 1;
        const int k0 = kt * 64;
#pragma unroll
        for (int i = 0; i < 4; i++) {
            int idx = t + i * 256;
            int r   = idx >> 4;
            int u   = idx & 15;
            uint32_t off = (uint32_t)(r * ASTR + u * 8) * 2;
            cp_async16(sb + OFF_KV(s) + off,       kbase + (size_t)(k0 + r) * KVSZ + u * 8);
            cp_async16(sb + OFF_KV(s) + AKB + off, vbase + (size_t)(k0 + r) * KVSZ + u * 8);
        }
        CP_COMMIT();
    };

    float m0 = -1e30f, m1 = -1e30f, l0 = 0.0f, l1 = 0.0f;
    float o[16][4];
#pragma unroll
    for (int i = 0; i < 16; i++)
#pragma unroll
        for (int j = 0; j < 4; j++) o[i][j] = 0.0f;

    issue_kv(0);
    for (int kt = 0; kt < nkv; kt++) {
        const int k0 = kt * 64;
        const int st = kt & 1;
        CP_WAIT0();
        __syncthreads();
        if (kt + 1 < nkv) issue_kv(kt + 1);

        float sacc[8][4];
#pragma unroll
        for (int i = 0; i < 8; i++)
#pragma unroll
            for (int j = 0; j < 4; j++) sacc[i][j] = 0.0f;

        const uint32_t aOff = (uint32_t)((wRow + (lane & 15)) * ASTR + (lane >> 4) * 8) * 2;
        const uint32_t bOff = (uint32_t)(((lane & 15)) * ASTR + (lane >> 4) * 8) * 2;
        const uint32_t kvK = sb + OFF_KV(st);
        const uint32_t kvV = kvK + AKB;
#pragma unroll
        for (int kk = 0; kk < 8; kk++) {
            const uint32_t ko = (uint32_t)(kk * 16) * 2;
            uint32_t qf[4];
            ldmatrix_x4(qf[0], qf[1], qf[2], qf[3], sb + OFF_Q + aOff + ko);
#pragma unroll
            for (int g = 0; g < 4; g++) {
                uint32_t off = bOff + (uint32_t)(g * 16 * ASTR) * 2 + ko;
                uint32_t kh[4];
                ldmatrix_x4(kh[0], kh[1], kh[2], kh[3], kvK + off);
                mma_f16(sacc[2 * g],     qf, kh[0], kh[2]);
                mma_f16(sacc[2 * g + 1], qf, kh[1], kh[3]);
            }
        }

        const int r0 = q0 + wRow + (lane >> 2);
        const int r1 = r0 + 8;
        if (k0 + 63 > q0 + wRow) {
#pragma unroll
            for (int nt = 0; nt < 8; nt++) {
                int c = k0 + nt * 8 + (lane & 3) * 2;
                if (c     > r0) sacc[nt][0] = -1e30f;
                if (c + 1 > r0) sacc[nt][1] = -1e30f;
                if (c     > r1) sacc[nt][2] = -1e30f;
                if (c + 1 > r1) sacc[nt][3] = -1e30f;
            }
        }

        float mx0 = m0, mx1 = m1;
#pragma unroll
        for (int nt = 0; nt < 8; nt++) {
            mx0 = fmaxf(mx0, fmaxf(sacc[nt][0], sacc[nt][1]));
            mx1 = fmaxf(mx1, fmaxf(sacc[nt][2], sacc[nt][3]));
        }
        mx0 = fmaxf(mx0, __shfl_xor_sync(0xFFFFFFFFu, mx0, 1));
        mx0 = fmaxf(mx0, __shfl_xor_sync(0xFFFFFFFFu, mx0, 2));
        mx1 = fmaxf(mx1, __shfl_xor_sync(0xFFFFFFFFu, mx1, 1));
        mx1 = fmaxf(mx1, __shfl_xor_sync(0xFFFFFFFFu, mx1, 2));
        float f0 = __expf(m0 - mx0), f1 = __expf(m1 - mx1);
        float sum0 = 0.0f, sum1 = 0.0f;
#pragma unroll
        for (int nt = 0; nt < 8; nt++) {
            sacc[nt][0] = __expf(sacc[nt][0] - mx0);
            sacc[nt][1] = __expf(sacc[nt][1] - mx0);
            sacc[nt][2] = __expf(sacc[nt][2] - mx1);
            sacc[nt][3] = __expf(sacc[nt][3] - mx1);
            sum0 += sacc[nt][0] + sacc[nt][1];
            sum1 += sacc[nt][2] + sacc[nt][3];
        }
        sum0 += __shfl_xor_sync(0xFFFFFFFFu, sum0, 1);
        sum0 += __shfl_xor_sync(0xFFFFFFFFu, sum0, 2);
        sum1 += __shfl_xor_sync(0xFFFFFFFFu, sum1, 1);
        sum1 += __shfl_xor_sync(0xFFFFFFFFu, sum1, 2);
        m0 = mx0; m1 = mx1;
        l0 = l0 * f0 + sum0;
        l1 = l1 * f1 + sum1;
#pragma unroll
        for (int d = 0; d < 16; d++) {
            o[d][0] *= f0; o[d][1] *= f0; o[d][2] *= f1; o[d][3] *= f1;
        }

#pragma unroll
        for (int kt2 = 0; kt2 < 4; kt2++) {
            uint32_t Ph[4];
            Ph[0] = pack_hi_h(sacc[2 * kt2][0],     sacc[2 * kt2][1]);
            Ph[1] = pack_hi_h(sacc[2 * kt2][2],     sacc[2 * kt2][3]);
            Ph[2] = pack_hi_h(sacc[2 * kt2 + 1][0], sacc[2 * kt2 + 1][1]);
            Ph[3] = pack_hi_h(sacc[2 * kt2 + 1][2], sacc[2 * kt2 + 1][3]);

            const int kRow = kt2 * 16 + (lane & 7) + ((lane >> 4) & 1) * 8;
#pragma unroll
            for (int gd = 0; gd < 8; gd++) {
                const int nCol = gd * 16 + ((lane >> 3) & 1) * 8;
                const uint32_t off = (uint32_t)(kRow * ASTR + nCol) * 2;
                uint32_t vh[4];
                ldmatrix_x4t(vh[0], vh[1], vh[2], vh[3], kvV + off);
                mma_f16(o[2 * gd],     Ph, vh[0], vh[2]);
                mma_f16(o[2 * gd + 1], Ph, vh[1], vh[3]);
            }
        }
    }

    const float i0 = 1.0f / l0, i1 = 1.0f / l1;
    const int tok0 = b * S_ + q0 + wRow + (lane >> 2);
    const int tok1 = tok0 + 8;
    const int colB = h * HD_ + (lane & 3) * 2;
#pragma unroll
    for (int d = 0; d < 16; d++) {
        int col = colB + d * 8;
        *(uint32_t*)(outh + (size_t)tok0 * QSZ + col) = pack_hi_h(o[d][0] * i0, o[d][1] * i0);
        *(uint32_t*)(outh + (size_t)tok1 * QSZ + col) = pack_hi_h(o[d][2] * i1, o[d][3] * i1);
    }
}

// ============================================================================
// kernel_launch
// ============================================================================
extern "C" void kernel_launch(void* const* d_in, const int* in_sizes, int n_in,
                              void* d_out, int out_size) {
    const float* hs    = (const float*)d_in[0];
    const float* cosb  = (const float*)d_in[1];
    const float* sinb  = (const float*)d_in[2];
    const float* w_qkv = (const float*)d_in[3];
    const float* w_o   = (const float*)d_in[4];
    float* out = (float*)d_out;

    __half *hsp, *wq, *wo, *qq, *kk, *vv, *at;
    cudaGetSymbolAddress((void**)&hsp, g_hs);
    cudaGetSymbolAddress((void**)&wq,  g_wq);
    cudaGetSymbolAddress((void**)&wo,  g_wo);
    cudaGetSymbolAddress((void**)&qq,  g_q);
    cudaGetSymbolAddress((void**)&kk,  g_k);
    cudaGetSymbolAddress((void**)&vv,  g_v);
    cudaGetSymbolAddress((void**)&at,  g_at);

    cudaFuncSetAttribute(gemm_qkv, cudaFuncAttributeMaxDynamicSharedMemorySize, GEMM_SMEM);
    cudaFuncSetAttribute(gemm_h1,  cudaFuncAttributeMaxDynamicSharedMemorySize, GEMM_SMEM);
    cudaFuncSetAttribute(attn_tc,  cudaFuncAttributeMaxDynamicSharedMemorySize, ATTN_SMEM);

    // 0) fused operand conversion
    cvt_all_kernel<<<(N4_TOTAL + 255) / 256, 256>>>(hs, w_qkv, w_o, hsp, wq, wo);

    // 1) QKV projection + fused RoPE + fp16 (M-blocks of 256)
    gemm_qkv<<<(TOK / 256) * (OSZ / 128), 512, GEMM_SMEM>>>(hsp, wq, cosb, sinb,
                                                            qq, kk, vv);

    // 2) Attention
    {
        dim3 grid(S_ / 128, B_ * NH_);
        attn_tc<<<grid, 256, ATTN_SMEM>>>(qq, kk, vv, at);
    }

    // 3) Output projection (M-blocks of 256)
    gemm_h1<<<(TOK / 256) * (HID_ / 128), 512, GEMM_SMEM>>>(at, wo, out,
                                                            HID_, QSZ, HID_ / 128);
}